// round 2
// baseline (speedup 1.0000x reference)
#include <cuda_runtime.h>

// RSLDS forward-backward smoother, B=8 T=1024 N=64 K=8.
// Outputs concatenated in d_out: forward(B,T,N,K) | backward(B,T,N,K) |
// gamma1(B,T,N,K) | gamma2(B,T,N,K,K)

#define FULLMASK 0xffffffffu
constexpr int B_ = 8, T_ = 1024, N_ = 64, K_ = 8;
constexpr long long BTNK = (long long)B_ * T_ * N_ * K_;

// logsumexp over the 8 distinct values indexed by rr = lane>>2 (replicated
// across ii = lane&3). xor 4/8/16 traverse the rr bits, so each distinct
// value is visited exactly once — no replication correction needed.
__device__ __forceinline__ float warp_lse_over_rr(float u) {
    float m = u;
    m = fmaxf(m, __shfl_xor_sync(FULLMASK, m, 4));
    m = fmaxf(m, __shfl_xor_sync(FULLMASK, m, 8));
    m = fmaxf(m, __shfl_xor_sync(FULLMASK, m, 16));
    float e = __expf(u - m);
    e += __shfl_xor_sync(FULLMASK, e, 4);
    e += __shfl_xor_sync(FULLMASK, e, 8);
    e += __shfl_xor_sync(FULLMASK, e, 16);
    return m + __logf(e);
}

// One warp = one chain (b,n), forward or backward, serial over T with
// depth-4 register prefetch of log_a/log_b.
__global__ void __launch_bounds__(128) fwbw_kernel(
    const float* __restrict__ la,   // (B,T,N,K,K)
    const float* __restrict__ lb,   // (B,T,N,K)
    const float* __restrict__ lz,   // (N,K)
    float* __restrict__ fw,
    float* __restrict__ bw)
{
    const int w    = blockIdx.x * (blockDim.x >> 5) + (threadIdx.x >> 5);
    const int lane = threadIdx.x & 31;
    const int ii   = lane & 3;     // sub-index (pairs of j for fw / pairs of i for bw)
    const int rr   = lane >> 2;    // i (fw) or j (bw), 0..7

    const bool is_bw = (w >= B_ * N_);
    const int  c = is_bw ? w - B_ * N_ : w;
    const int  b = c / N_;
    const int  n = c % N_;
    const long long chain = (long long)b * T_ * N_ + n;  // (b, t=0, n) in tile units

    if (!is_bw) {
        // ---------------- forward ----------------
        // lane (i=rr, jj=ii) handles terms j = 2*ii, 2*ii+1 of row i.
        long long base0 = chain;
        float v = lz[n * K_ + rr] + lb[base0 * K_ + rr];
        float prev = v - warp_lse_over_rr(v);
        if (ii == 0) fw[base0 * K_ + rr] = prev;

        float2 abuf[4];
        float  bbuf[4];
        #pragma unroll
        for (int u = 0; u < 4; u++) {
            long long bt = chain + (long long)(1 + u) * N_;
            abuf[u] = *(const float2*)(la + bt * 64 + lane * 2);
            bbuf[u] = lb[bt * K_ + rr];
        }

        for (int tb = 1; tb < T_; tb += 4) {
            #pragma unroll
            for (int u = 0; u < 4; u++) {
                int t = tb + u;
                if (t >= T_) break;
                float2 av = abuf[u];
                float  bv = bbuf[u];
                int tn = t + 4;
                if (tn < T_) {
                    long long bt = chain + (long long)tn * N_;
                    abuf[u] = *(const float2*)(la + bt * 64 + lane * 2);
                    bbuf[u] = lb[bt * K_ + rr];
                }
                // prev_j broadcasts: prev for state j lives at lane j*4
                float p0 = __shfl_sync(FULLMASK, prev, ii * 8);
                float p1 = __shfl_sync(FULLMASK, prev, ii * 8 + 4);
                float t0 = av.x + p0;
                float t1 = av.y + p1;
                // logsumexp over j within the 4-lane group (8 terms total)
                float m = fmaxf(t0, t1);
                m = fmaxf(m, __shfl_xor_sync(FULLMASK, m, 1));
                m = fmaxf(m, __shfl_xor_sync(FULLMASK, m, 2));
                float e = __expf(t0 - m) + __expf(t1 - m);
                e += __shfl_xor_sync(FULLMASK, e, 1);
                e += __shfl_xor_sync(FULLMASK, e, 2);
                float uu = bv + m + __logf(e);
                prev = uu - warp_lse_over_rr(uu);
                if (ii == 0) fw[(chain + (long long)t * N_) * K_ + rr] = prev;
            }
        }
    } else {
        // ---------------- backward ----------------
        // lane (j=rr, ii) handles terms i = 2*ii, 2*ii+1 of column j.
        long long baseT = chain + (long long)(T_ - 1) * N_;
        float prev = 0.0f;
        if (ii == 0) bw[baseT * K_ + rr] = 0.0f;

        float  c0buf[4], c1buf[4];
        float2 bbuf[4];
        #pragma unroll
        for (int u = 0; u < 4; u++) {
            int t = T_ - 2 - u;                      // uses data at t+1
            long long bt = chain + (long long)(t + 1) * N_;
            c0buf[u] = la[bt * 64 + ii * 16 + rr];       // a[2ii][j]
            c1buf[u] = la[bt * 64 + ii * 16 + 8 + rr];   // a[2ii+1][j]
            bbuf[u]  = *(const float2*)(lb + bt * K_ + ii * 2);
        }

        for (int tb = T_ - 2; tb >= 0; tb -= 4) {
            #pragma unroll
            for (int u = 0; u < 4; u++) {
                int t = tb - u;
                if (t < 0) break;
                float  cc0 = c0buf[u], cc1 = c1buf[u];
                float2 bv = bbuf[u];
                int tn = t - 4;
                if (tn >= 0) {
                    long long bt = chain + (long long)(tn + 1) * N_;
                    c0buf[u] = la[bt * 64 + ii * 16 + rr];
                    c1buf[u] = la[bt * 64 + ii * 16 + 8 + rr];
                    bbuf[u]  = *(const float2*)(lb + bt * K_ + ii * 2);
                }
                // s_i = beta_{t+1}[i] + b_{t+1}[i]; beta for state i at lane i*4
                float s0 = __shfl_sync(FULLMASK, prev, ii * 8) + bv.x;
                float s1 = __shfl_sync(FULLMASK, prev, ii * 8 + 4) + bv.y;
                float t0 = cc0 + s0;
                float t1 = cc1 + s1;
                float m = fmaxf(t0, t1);
                m = fmaxf(m, __shfl_xor_sync(FULLMASK, m, 1));
                m = fmaxf(m, __shfl_xor_sync(FULLMASK, m, 2));
                float e = __expf(t0 - m) + __expf(t1 - m);
                e += __shfl_xor_sync(FULLMASK, e, 1);
                e += __shfl_xor_sync(FULLMASK, e, 2);
                float uu = m + __logf(e);
                prev = uu - warp_lse_over_rr(uu);
                if (ii == 0) bw[(chain + (long long)t * N_) * K_ + rr] = prev;
            }
        }
    }
}

// Posteriors: one warp handles 4 consecutive-n tiles at the same (b,t).
// Each 8-lane group owns one tile; lane r owns row i=r (8 j-terms).
__global__ void __launch_bounds__(256) gamma_kernel(
    const float* __restrict__ la,
    const float* __restrict__ lb,
    const float* __restrict__ fw,
    const float* __restrict__ bwp,
    float* __restrict__ g1,
    float* __restrict__ g2)
{
    const int w    = blockIdx.x * (blockDim.x >> 5) + (threadIdx.x >> 5);
    const int lane = threadIdx.x & 31;
    const int grp  = lane >> 3;
    const int r    = lane & 7;

    const int nt    = w % (N_ / 4);
    const int btile = w / (N_ / 4);
    const int t     = btile % T_;
    const int b     = btile / T_;
    const int n     = nt * 4 + grp;
    const long long base = ((long long)b * T_ + t) * N_ + n;

    const float fwv = fw[base * K_ + r];
    const float bwv = bwp[base * K_ + r];

    // gamma1 = normalize(fw + bw) over K within the 8-lane group
    float v = fwv + bwv;
    float m1 = v;
    m1 = fmaxf(m1, __shfl_xor_sync(FULLMASK, m1, 1));
    m1 = fmaxf(m1, __shfl_xor_sync(FULLMASK, m1, 2));
    m1 = fmaxf(m1, __shfl_xor_sync(FULLMASK, m1, 4));
    float e1 = __expf(v - m1);
    e1 += __shfl_xor_sync(FULLMASK, e1, 1);
    e1 += __shfl_xor_sync(FULLMASK, e1, 2);
    e1 += __shfl_xor_sync(FULLMASK, e1, 4);
    g1[base * K_ + r] = v - (m1 + __logf(e1));

    float4* g2p = (float4*)(g2 + base * 64 + r * 8);
    if (t == 0) {                       // warp-uniform branch
        float4 z = make_float4(0.f, 0.f, 0.f, 0.f);
        g2p[0] = z;
        g2p[1] = z;
        return;
    }

    const float fwp = fw[(base - N_) * K_ + r];      // forward at t-1, state r
    const float s   = bwv + lb[base * K_ + r];       // bw_t[i=r] + log_b_t[i=r]
    const float4* pa = (const float4*)(la + base * 64 + r * 8);
    float av[8];
    *(float4*)&av[0] = pa[0];
    *(float4*)&av[4] = pa[1];

    float g[8];
    #pragma unroll
    for (int j = 0; j < 8; j++)
        g[j] = av[j] + __shfl_sync(FULLMASK, fwp, j, 8) + s;

    float m = g[0];
    #pragma unroll
    for (int j = 1; j < 8; j++) m = fmaxf(m, g[j]);
    m = fmaxf(m, __shfl_xor_sync(FULLMASK, m, 1));
    m = fmaxf(m, __shfl_xor_sync(FULLMASK, m, 2));
    m = fmaxf(m, __shfl_xor_sync(FULLMASK, m, 4));
    float e = 0.f;
    #pragma unroll
    for (int j = 0; j < 8; j++) e += __expf(g[j] - m);
    e += __shfl_xor_sync(FULLMASK, e, 1);
    e += __shfl_xor_sync(FULLMASK, e, 2);
    e += __shfl_xor_sync(FULLMASK, e, 4);
    const float lse = m + __logf(e);

    float4 o0 = make_float4(g[0] - lse, g[1] - lse, g[2] - lse, g[3] - lse);
    float4 o1 = make_float4(g[4] - lse, g[5] - lse, g[6] - lse, g[7] - lse);
    g2p[0] = o0;
    g2p[1] = o1;
}

extern "C" void kernel_launch(void* const* d_in, const int* in_sizes, int n_in,
                              void* d_out, int out_size) {
    const float* la = (const float*)d_in[0];   // log_a  (B,T,N,K,K)
    const float* lb = (const float*)d_in[1];   // log_b  (B,T,N,K)
    const float* lz = (const float*)d_in[2];   // logprob_z1 (N,K)

    float* out = (float*)d_out;
    float* fw = out;
    float* bw = fw + BTNK;
    float* g1 = bw + BTNK;
    float* g2 = g1 + BTNK;

    // 1024 chain-warps (512 fw + 512 bw), 4 warps/block
    fwbw_kernel<<<(2 * B_ * N_) / 4, 128>>>(la, lb, lz, fw, bw);

    // B*T*N/4 = 131072 warps, 8 warps/block
    gamma_kernel<<<(B_ * T_ * (N_ / 4)) / 8, 256>>>(la, lb, fw, bw, g1, g2);
}